// round 14
// baseline (speedup 1.0000x reference)
#include <cuda_runtime.h>
#include <cstdint>
#include <math.h>

#define Bb 16
#define Ff 128
#define Nn 2048
#define BN (Bb*Nn)          // 32768
#define TOT (Bb*Ff*Nn)      // 4194304
#define NBLK 128            // k_fused grid size
#define TILE_N 256
#define TILE_BYTES (Ff * TILE_N * 4)   // 128KB smem tile

// scratch (allocation-free: __device__ globals)
__device__ float g_s[BN];
__device__ float g_E[BN];
__device__ float g_psum[NBLK];
__device__ float g_psq[NBLK];

// ---------------------------------------------------------------------------
// Pass 1: s[b,n] = sum_f v[f]*emb[b,f,n]; per-block partial sum/sumsq.
// Reads via cp.async.bulk (TMA path, global->smem DMA): bypasses the L1tex
// sector-wavefront machinery that pinned all 5 prior read variants at 2.3TB/s.
// Grid = 128 blocks (16 b x 8 n-groups of 256). Block = 512 threads.
// ---------------------------------------------------------------------------
__global__ void __launch_bounds__(512) k_fused(const float* __restrict__ emb,
                                               const float* __restrict__ v) {
    extern __shared__ float stile[];            // [128 f][256 n] = 128KB
    __shared__ float sv[Ff];
    __shared__ float s2[2][TILE_N];
    __shared__ float red_sum[16];
    __shared__ float red_sq[16];
    __shared__ __align__(8) unsigned long long mbar;

    int tid = threadIdx.x;
    unsigned int mb = (unsigned int)__cvta_generic_to_shared(&mbar);

    if (tid < Ff) sv[tid] = v[tid];
    if (tid == 0)
        asm volatile("mbarrier.init.shared.b64 [%0], 1;" :: "r"(mb) : "memory");
    __syncthreads();

    int b  = blockIdx.x >> 3;          // 0..15
    int ng = blockIdx.x & 7;           // 0..7 (group of 256 n)

    // single elected thread: expect_tx + 128 bulk copies of 1KB (one per f)
    if (tid == 0) {
        asm volatile("mbarrier.arrive.expect_tx.shared.b64 _, [%0], %1;"
                     :: "r"(mb), "r"((unsigned int)TILE_BYTES) : "memory");
        unsigned int sbase = (unsigned int)__cvta_generic_to_shared(stile);
        const char* src = (const char*)(emb + (size_t)b * Ff * Nn + ng * TILE_N);
        for (int f = 0; f < Ff; f++) {
            asm volatile(
                "cp.async.bulk.shared::cta.global.mbarrier::complete_tx::bytes "
                "[%0], [%1], %2, [%3];"
                :: "r"(sbase + (unsigned int)(f * TILE_N * 4)),
                   "l"(src + (size_t)f * Nn * 4),
                   "r"((unsigned int)(TILE_N * 4)),
                   "r"(mb)
                : "memory");
        }
    }
    // all threads wait for tile completion (parity 0, acquire)
    {
        unsigned int par = 0;
        asm volatile(
            "{\n\t"
            ".reg .pred P;\n\t"
            "WL_%=:\n\t"
            "mbarrier.try_wait.parity.acquire.cta.shared::cta.b64 P, [%0], %1;\n\t"
            "@P bra WD_%=;\n\t"
            "bra WL_%=;\n\t"
            "WD_%=:\n\t"
            "}"
            :: "r"(mb), "r"(par) : "memory");
    }

    // compute from smem: thread = (half of f, n); warp rows 128B conflict-free
    int n    = tid & (TILE_N - 1);     // 0..255
    int half = tid >> 8;               // 0..1 (f 0-63 / 64-127)
    const float* base = stile + half * 64 * TILE_N + n;
    const float* pv   = sv + half * 64;

    float s = 0.f, sum = 0.f, sq = 0.f;
#pragma unroll 16
    for (int f = 0; f < 64; f++) {
        float x = base[(size_t)f * TILE_N];
        s   = fmaf(pv[f], x, s);
        sum += x;
        sq  = fmaf(x, x, sq);
    }
    s2[half][n] = s;
    __syncthreads();
    if (tid < TILE_N)
        g_s[b * Nn + ng * TILE_N + tid] = s2[0][tid] + s2[1][tid];

    // block reduce sum & sq -> per-block partial stores
    int lane = tid & 31;
    int wid  = tid >> 5;
#pragma unroll
    for (int o = 16; o > 0; o >>= 1) {
        sum += __shfl_xor_sync(0xffffffffu, sum, o);
        sq  += __shfl_xor_sync(0xffffffffu, sq, o);
    }
    if (lane == 0) { red_sum[wid] = sum; red_sq[wid] = sq; }
    __syncthreads();
    if (wid == 0) {
        float rs = (lane < 16) ? red_sum[lane] : 0.f;
        float rq = (lane < 16) ? red_sq[lane]  : 0.f;
#pragma unroll
        for (int o = 8; o > 0; o >>= 1) {
            rs += __shfl_xor_sync(0xffffffffu, rs, o);
            rq += __shfl_xor_sync(0xffffffffu, rq, o);
        }
        if (lane == 0) {
            g_psum[blockIdx.x] = rs;
            g_psq[blockIdx.x]  = rq;
        }
    }
}

// ---------------------------------------------------------------------------
// Pass 2: 64 blocks x 512 thr. Each block redundantly reduces the 128
// L2-resident partials -> scale, then E[n] = exp(-(s[n]*scale + bias/2)).
// ---------------------------------------------------------------------------
__global__ void __launch_bounds__(512) k_exp(const float* __restrict__ bias) {
    __shared__ float red_sum[16];
    __shared__ float red_sq[16];
    __shared__ float sh_scale, sh_hb;

    int tid  = threadIdx.x;
    int lane = tid & 31;
    int wid  = tid >> 5;

    float sum = (tid < NBLK) ? g_psum[tid] : 0.f;
    float sq  = (tid < NBLK) ? g_psq[tid]  : 0.f;
#pragma unroll
    for (int o = 16; o > 0; o >>= 1) {
        sum += __shfl_xor_sync(0xffffffffu, sum, o);
        sq  += __shfl_xor_sync(0xffffffffu, sq, o);
    }
    if (lane == 0) { red_sum[wid] = sum; red_sq[wid] = sq; }
    __syncthreads();
    if (tid == 0) {
        double ds = 0.0, dq = 0.0;
#pragma unroll
        for (int w = 0; w < 16; w++) { ds += (double)red_sum[w]; dq += (double)red_sq[w]; }
        double m   = (double)TOT;
        double var = (dq - ds * ds / m) / (m - 1.0);
        sh_scale = (float)(1.0 / sqrt(var));
        sh_hb    = 0.5f * bias[0];
    }
    __syncthreads();

    int idx = blockIdx.x * 512 + tid;   // 64 * 512 = 32768 = BN
    float t = fmaf(g_s[idx], sh_scale, sh_hb);
    g_E[idx] = __expf(-t);
}

// ---------------------------------------------------------------------------
// Pass 3: out[b,i,j] = 1/(1 + E_i*E_j). R3's proven-fastest shape: 4 rows per
// block, precomputed E, plain float4 stores. Sits at the DRAM write floor.
// ---------------------------------------------------------------------------
__device__ __forceinline__ float frcp(float x) {
    float r;
    asm("rcp.approx.f32 %0, %1;" : "=f"(r) : "f"(x));
    return r;
}

__global__ void __launch_bounds__(512) k_main(float* __restrict__ out) {
    int r0 = blockIdx.x << 2;          // first of 4 rows
    int b  = r0 >> 11;

    const float4* Erow = (const float4*)(g_E + (size_t)b * Nn);
    float4 ej = __ldg(Erow + threadIdx.x);

    float p0 = __ldg(g_E + r0);
    float p1 = __ldg(g_E + r0 + 1);
    float p2 = __ldg(g_E + r0 + 2);
    float p3 = __ldg(g_E + r0 + 3);

    float4 o0, o1, o2, o3;
    o0.x = frcp(fmaf(p0, ej.x, 1.f)); o0.y = frcp(fmaf(p0, ej.y, 1.f));
    o0.z = frcp(fmaf(p0, ej.z, 1.f)); o0.w = frcp(fmaf(p0, ej.w, 1.f));
    o1.x = frcp(fmaf(p1, ej.x, 1.f)); o1.y = frcp(fmaf(p1, ej.y, 1.f));
    o1.z = frcp(fmaf(p1, ej.z, 1.f)); o1.w = frcp(fmaf(p1, ej.w, 1.f));
    o2.x = frcp(fmaf(p2, ej.x, 1.f)); o2.y = frcp(fmaf(p2, ej.y, 1.f));
    o2.z = frcp(fmaf(p2, ej.z, 1.f)); o2.w = frcp(fmaf(p2, ej.w, 1.f));
    o3.x = frcp(fmaf(p3, ej.x, 1.f)); o3.y = frcp(fmaf(p3, ej.y, 1.f));
    o3.z = frcp(fmaf(p3, ej.z, 1.f)); o3.w = frcp(fmaf(p3, ej.w, 1.f));

    float4* orow = (float4*)(out + (size_t)r0 * Nn) + threadIdx.x;
    orow[0]          = o0;
    orow[Nn / 4]     = o1;
    orow[Nn / 2]     = o2;
    orow[3 * Nn / 4] = o3;
}

extern "C" void kernel_launch(void* const* d_in, const int* in_sizes, int n_in,
                              void* d_out, int out_size) {
    // inputs: adj_in [B,N,N] (unused), emb_in [B,F,N], v [F], b [1]
    const float* emb  = (const float*)d_in[1];
    const float* v    = (const float*)d_in[2];
    const float* bias = (const float*)d_in[3];
    float* out = (float*)d_out;

    static int smem_set = 0;
    if (!smem_set) {
        cudaFuncSetAttribute(k_fused, cudaFuncAttributeMaxDynamicSharedMemorySize,
                             TILE_BYTES);
        smem_set = 1;
    }

    k_fused<<<NBLK, 512, TILE_BYTES>>>(emb, v);
    k_exp<<<BN / 512, 512>>>(bias);
    k_main<<<BN / 4, 512>>>(out);
}

// round 15
// speedup vs baseline: 1.0371x; 1.0371x over previous
#include <cuda_runtime.h>
#include <cstdint>
#include <math.h>

#define Bb 16
#define Ff 128
#define Nn 2048
#define BN (Bb*Nn)          // 32768
#define TOT (Bb*Ff*Nn)      // 4194304
#define NBLK 512            // k_fused grid size

// scratch (allocation-free: __device__ globals)
__device__ float g_s[BN];
__device__ float g_E[BN];
__device__ float g_psum[NBLK];
__device__ float g_psq[NBLK];

// ---------------------------------------------------------------------------
// Pass 1: s[b,n] = sum_f v[f]*emb[b,f,n]; per-block partial sum/sumsq.
// LDG.128 AT FULL OCCUPANCY: 512 blocks x 512 threads (55 warps/SM; R4/R8's
// float4 attempts were grid-starved at 27 warps/SM). 4 x LDG.128 per thread.
// Block = (b, 64-n group): 512 thr = 32 fc (4 f each) x 16 float4 (64 n).
// ---------------------------------------------------------------------------
__global__ void __launch_bounds__(512) k_fused(const float* __restrict__ emb,
                                               const float* __restrict__ v) {
    __shared__ float  sv[Ff];
    __shared__ float4 spart[32][16];   // [fc][col] 8KB
    __shared__ float  red_sum[16];
    __shared__ float  red_sq[16];

    int tid = threadIdx.x;
    if (tid < Ff) sv[tid] = v[tid];
    __syncthreads();

    int b   = blockIdx.x >> 5;         // 0..15
    int ng  = blockIdx.x & 31;         // 0..31 (group of 64 n)
    int fc  = tid >> 4;                // 0..31 (4 f each)
    int col = tid & 15;                // 0..15 (float4 within 64-n group)

    const float4* p = (const float4*)(emb + ((size_t)(b * Ff + fc * 4)) * Nn
                                          + ng * 64) + col;
    const float* pv = sv + fc * 4;

    float4 s4 = make_float4(0.f, 0.f, 0.f, 0.f);
    float sum = 0.f, sq = 0.f;
#pragma unroll
    for (int f = 0; f < 4; f++) {
        float4 x = __ldg(p + (size_t)f * (Nn / 4));
        float vf = pv[f];
        s4.x = fmaf(vf, x.x, s4.x);
        s4.y = fmaf(vf, x.y, s4.y);
        s4.z = fmaf(vf, x.z, s4.z);
        s4.w = fmaf(vf, x.w, s4.w);
        sum += (x.x + x.y) + (x.z + x.w);
        sq = fmaf(x.x, x.x, sq);
        sq = fmaf(x.y, x.y, sq);
        sq = fmaf(x.z, x.z, sq);
        sq = fmaf(x.w, x.w, sq);
    }
    spart[fc][col] = s4;
    __syncthreads();

    // tree reduce over 32 fc (5 steps)
#pragma unroll
    for (int st = 16; st > 0; st >>= 1) {
        if (fc < st) {
            float4 a = spart[fc][col];
            float4 c = spart[fc + st][col];
            a.x += c.x; a.y += c.y; a.z += c.z; a.w += c.w;
            spart[fc][col] = a;
        }
        __syncthreads();
    }
    if (fc == 0)
        ((float4*)(g_s + (size_t)b * Nn + ng * 64))[col] = spart[0][col];

    // block reduce sum & sq -> plain per-block stores
    int lane = tid & 31;
    int wid  = tid >> 5;
#pragma unroll
    for (int o = 16; o > 0; o >>= 1) {
        sum += __shfl_xor_sync(0xffffffffu, sum, o);
        sq  += __shfl_xor_sync(0xffffffffu, sq, o);
    }
    if (lane == 0) { red_sum[wid] = sum; red_sq[wid] = sq; }
    __syncthreads();
    if (wid == 0) {
        float rs = (lane < 16) ? red_sum[lane] : 0.f;
        float rq = (lane < 16) ? red_sq[lane]  : 0.f;
#pragma unroll
        for (int o = 8; o > 0; o >>= 1) {
            rs += __shfl_xor_sync(0xffffffffu, rs, o);
            rq += __shfl_xor_sync(0xffffffffu, rq, o);
        }
        if (lane == 0) {
            g_psum[blockIdx.x] = rs;
            g_psq[blockIdx.x]  = rq;
        }
    }
}

// ---------------------------------------------------------------------------
// Pass 2: 128 blocks x 256 thr. Each block redundantly reduces the 512
// L2-resident partials -> scale, then E[n] = exp(-(s[n]*scale + bias/2)).
// ---------------------------------------------------------------------------
__global__ void __launch_bounds__(256) k_exp(const float* __restrict__ bias) {
    __shared__ float red_sum[8];
    __shared__ float red_sq[8];
    __shared__ float sh_scale, sh_hb;

    int tid  = threadIdx.x;
    int lane = tid & 31;
    int wid  = tid >> 5;

    float sum = g_psum[tid] + g_psum[tid + 256];
    float sq  = g_psq[tid]  + g_psq[tid + 256];
#pragma unroll
    for (int o = 16; o > 0; o >>= 1) {
        sum += __shfl_xor_sync(0xffffffffu, sum, o);
        sq  += __shfl_xor_sync(0xffffffffu, sq, o);
    }
    if (lane == 0) { red_sum[wid] = sum; red_sq[wid] = sq; }
    __syncthreads();
    if (tid == 0) {
        double ds = 0.0, dq = 0.0;
#pragma unroll
        for (int w = 0; w < 8; w++) { ds += (double)red_sum[w]; dq += (double)red_sq[w]; }
        double m   = (double)TOT;
        double var = (dq - ds * ds / m) / (m - 1.0);
        sh_scale = (float)(1.0 / sqrt(var));
        sh_hb    = 0.5f * bias[0];
    }
    __syncthreads();

    int idx = blockIdx.x * 256 + tid;
    float t = fmaf(g_s[idx], sh_scale, sh_hb);
    g_E[idx] = __expf(-t);
}

// ---------------------------------------------------------------------------
// Pass 3: out[b,i,j] = 1/(1 + E_i*E_j). R3 verbatim (proven fastest, at the
// DRAM write floor): 4 rows per block, no syncs, plain float4 stores.
// ---------------------------------------------------------------------------
__device__ __forceinline__ float frcp(float x) {
    float r;
    asm("rcp.approx.f32 %0, %1;" : "=f"(r) : "f"(x));
    return r;
}

__global__ void __launch_bounds__(512) k_main(float* __restrict__ out) {
    int r0 = blockIdx.x << 2;          // first of 4 rows
    int b  = r0 >> 11;

    const float4* Erow = (const float4*)(g_E + (size_t)b * Nn);
    float4 ej = __ldg(Erow + threadIdx.x);

    float p0 = __ldg(g_E + r0);
    float p1 = __ldg(g_E + r0 + 1);
    float p2 = __ldg(g_E + r0 + 2);
    float p3 = __ldg(g_E + r0 + 3);

    float4 o0, o1, o2, o3;
    o0.x = frcp(fmaf(p0, ej.x, 1.f)); o0.y = frcp(fmaf(p0, ej.y, 1.f));
    o0.z = frcp(fmaf(p0, ej.z, 1.f)); o0.w = frcp(fmaf(p0, ej.w, 1.f));
    o1.x = frcp(fmaf(p1, ej.x, 1.f)); o1.y = frcp(fmaf(p1, ej.y, 1.f));
    o1.z = frcp(fmaf(p1, ej.z, 1.f)); o1.w = frcp(fmaf(p1, ej.w, 1.f));
    o2.x = frcp(fmaf(p2, ej.x, 1.f)); o2.y = frcp(fmaf(p2, ej.y, 1.f));
    o2.z = frcp(fmaf(p2, ej.z, 1.f)); o2.w = frcp(fmaf(p2, ej.w, 1.f));
    o3.x = frcp(fmaf(p3, ej.x, 1.f)); o3.y = frcp(fmaf(p3, ej.y, 1.f));
    o3.z = frcp(fmaf(p3, ej.z, 1.f)); o3.w = frcp(fmaf(p3, ej.w, 1.f));

    float4* orow = (float4*)(out + (size_t)r0 * Nn) + threadIdx.x;
    orow[0]          = o0;
    orow[Nn / 4]     = o1;
    orow[Nn / 2]     = o2;
    orow[3 * Nn / 4] = o3;
}

extern "C" void kernel_launch(void* const* d_in, const int* in_sizes, int n_in,
                              void* d_out, int out_size) {
    // inputs: adj_in [B,N,N] (unused), emb_in [B,F,N], v [F], b [1]
    const float* emb  = (const float*)d_in[1];
    const float* v    = (const float*)d_in[2];
    const float* bias = (const float*)d_in[3];
    float* out = (float*)d_out;

    k_fused<<<NBLK, 512>>>(emb, v);
    k_exp<<<BN / 256, 256>>>(bias);
    k_main<<<BN / 4, 512>>>(out);
}

// round 16
// speedup vs baseline: 1.0462x; 1.0087x over previous
#include <cuda_runtime.h>
#include <cstdint>
#include <math.h>

#define Bb 16
#define Ff 128
#define Nn 2048
#define BN (Bb*Nn)          // 32768
#define TOT (Bb*Ff*Nn)      // 4194304
#define NBLK 512            // k_fused grid size

// scratch (allocation-free: __device__ globals)
__device__ float g_s[BN];
__device__ float g_E[BN];
__device__ float g_psum[NBLK];
__device__ float g_psq[NBLK];

// ---------------------------------------------------------------------------
// Pass 1 (best measured: 6.98us, R13): s[b,n] = sum_f v[f]*emb[b,f,n];
// per-block partial sum/sumsq. 512 blocks x 512 thr = 8 fc (16 f) x 64 n.
// Scalar LDG is the proven floor (float4/cp.async/TMA all slower).
// ---------------------------------------------------------------------------
__global__ void __launch_bounds__(512) k_fused(const float* __restrict__ emb,
                                               const float* __restrict__ v) {
    __shared__ float sv[Ff];
    __shared__ float spart[512];
    __shared__ float red_sum[16];
    __shared__ float red_sq[16];

    int tid = threadIdx.x;
    if (tid < Ff) sv[tid] = v[tid];
    __syncthreads();

    int b  = blockIdx.x >> 5;          // 0..15
    int ng = blockIdx.x & 31;          // 0..31 (group of 64 n)
    int nl = tid & 63;                 // 0..63
    int fc = tid >> 6;                 // 0..7  (f-chunk of 16)
    int n  = ng * 64 + nl;

    const float* p  = emb + ((size_t)(b * Ff + fc * 16)) * Nn + n;
    const float* pv = sv + fc * 16;

    float s = 0.f, sum = 0.f, sq = 0.f;
#pragma unroll
    for (int f = 0; f < 16; f++) {
        float x = __ldg(p + (size_t)f * Nn);
        s   = fmaf(pv[f], x, s);
        sum += x;
        sq  = fmaf(x, x, sq);
    }
    spart[tid] = s;
    __syncthreads();
    if (tid < 64) {
        float tot = 0.f;
#pragma unroll
        for (int c = 0; c < 8; c++) tot += spart[c * 64 + tid];
        g_s[b * Nn + ng * 64 + tid] = tot;
    }

    // block reduce sum & sq -> plain per-block stores
    int lane = tid & 31;
    int wid  = tid >> 5;
#pragma unroll
    for (int o = 16; o > 0; o >>= 1) {
        sum += __shfl_xor_sync(0xffffffffu, sum, o);
        sq  += __shfl_xor_sync(0xffffffffu, sq, o);
    }
    if (lane == 0) { red_sum[wid] = sum; red_sq[wid] = sq; }
    __syncthreads();
    if (wid == 0) {
        float rs = (lane < 16) ? red_sum[lane] : 0.f;
        float rq = (lane < 16) ? red_sq[lane]  : 0.f;
#pragma unroll
        for (int o = 8; o > 0; o >>= 1) {
            rs += __shfl_xor_sync(0xffffffffu, rs, o);
            rq += __shfl_xor_sync(0xffffffffu, rq, o);
        }
        if (lane == 0) {
            g_psum[blockIdx.x] = rs;
            g_psq[blockIdx.x]  = rq;
        }
    }
}

// ---------------------------------------------------------------------------
// Pass 2: 64 blocks x 512 thr. Each block redundantly reduces the 512
// L2-resident partials (one per thread) -> scale, then
// E[n] = exp(-(s[n]*scale + bias/2)).
// ---------------------------------------------------------------------------
__global__ void __launch_bounds__(512) k_exp(const float* __restrict__ bias) {
    __shared__ float red_sum[16];
    __shared__ float red_sq[16];
    __shared__ float sh_scale, sh_hb;

    int tid  = threadIdx.x;
    int lane = tid & 31;
    int wid  = tid >> 5;

    float sum = g_psum[tid];
    float sq  = g_psq[tid];
#pragma unroll
    for (int o = 16; o > 0; o >>= 1) {
        sum += __shfl_xor_sync(0xffffffffu, sum, o);
        sq  += __shfl_xor_sync(0xffffffffu, sq, o);
    }
    if (lane == 0) { red_sum[wid] = sum; red_sq[wid] = sq; }
    __syncthreads();
    if (tid == 0) {
        double ds = 0.0, dq = 0.0;
#pragma unroll
        for (int w = 0; w < 16; w++) { ds += (double)red_sum[w]; dq += (double)red_sq[w]; }
        double m   = (double)TOT;
        double var = (dq - ds * ds / m) / (m - 1.0);
        sh_scale = (float)(1.0 / sqrt(var));
        sh_hb    = 0.5f * bias[0];
    }
    __syncthreads();

    int idx = blockIdx.x * 512 + tid;   // 64 * 512 = 32768 = BN
    float t = fmaf(g_s[idx], sh_scale, sh_hb);
    g_E[idx] = __expf(-t);
}

// ---------------------------------------------------------------------------
// Pass 3 (R3 verbatim — every deviation regressed): out = 1/(1 + E_i*E_j).
// 4 rows per block, no syncs, precomputed E, plain float4 stores.
// At the HBM write ceiling (~6.4 TB/s on the 256MB stream).
// ---------------------------------------------------------------------------
__device__ __forceinline__ float frcp(float x) {
    float r;
    asm("rcp.approx.f32 %0, %1;" : "=f"(r) : "f"(x));
    return r;
}

__global__ void __launch_bounds__(512) k_main(float* __restrict__ out) {
    int r0 = blockIdx.x << 2;          // first of 4 rows
    int b  = r0 >> 11;

    const float4* Erow = (const float4*)(g_E + (size_t)b * Nn);
    float4 ej = __ldg(Erow + threadIdx.x);

    float p0 = __ldg(g_E + r0);
    float p1 = __ldg(g_E + r0 + 1);
    float p2 = __ldg(g_E + r0 + 2);
    float p3 = __ldg(g_E + r0 + 3);

    float4 o0, o1, o2, o3;
    o0.x = frcp(fmaf(p0, ej.x, 1.f)); o0.y = frcp(fmaf(p0, ej.y, 1.f));
    o0.z = frcp(fmaf(p0, ej.z, 1.f)); o0.w = frcp(fmaf(p0, ej.w, 1.f));
    o1.x = frcp(fmaf(p1, ej.x, 1.f)); o1.y = frcp(fmaf(p1, ej.y, 1.f));
    o1.z = frcp(fmaf(p1, ej.z, 1.f)); o1.w = frcp(fmaf(p1, ej.w, 1.f));
    o2.x = frcp(fmaf(p2, ej.x, 1.f)); o2.y = frcp(fmaf(p2, ej.y, 1.f));
    o2.z = frcp(fmaf(p2, ej.z, 1.f)); o2.w = frcp(fmaf(p2, ej.w, 1.f));
    o3.x = frcp(fmaf(p3, ej.x, 1.f)); o3.y = frcp(fmaf(p3, ej.y, 1.f));
    o3.z = frcp(fmaf(p3, ej.z, 1.f)); o3.w = frcp(fmaf(p3, ej.w, 1.f));

    float4* orow = (float4*)(out + (size_t)r0 * Nn) + threadIdx.x;
    orow[0]          = o0;
    orow[Nn / 4]     = o1;
    orow[Nn / 2]     = o2;
    orow[3 * Nn / 4] = o3;
}

extern "C" void kernel_launch(void* const* d_in, const int* in_sizes, int n_in,
                              void* d_out, int out_size) {
    // inputs: adj_in [B,N,N] (unused), emb_in [B,F,N], v [F], b [1]
    const float* emb  = (const float*)d_in[1];
    const float* v    = (const float*)d_in[2];
    const float* bias = (const float*)d_in[3];
    float* out = (float*)d_out;

    k_fused<<<NBLK, 512>>>(emb, v);
    k_exp<<<BN / 512, 512>>>(bias);
    k_main<<<BN / 4, 512>>>(out);
}

// round 17
// speedup vs baseline: 1.0897x; 1.0416x over previous
#include <cuda_runtime.h>
#include <math.h>

#define Bb 16
#define Ff 128
#define Nn 2048
#define BN (Bb*Nn)          // 32768
#define TOT (Bb*Ff*Nn)      // 4194304

// scratch (allocation-free: __device__ globals)
__device__ float  g_s[BN];
__device__ float  g_E[BN];
__device__ double g_sum   = 0.0;
__device__ double g_sumsq = 0.0;

// ---------------------------------------------------------------------------
// Pass 1: s[b,n] = sum_f v[f]*emb[b,f,n]; accumulate global sum / sumsq.
// Measured-champion config (49.3us total): 256 thr = 4 fc (32 f) x 64 n,
// grid 512, scalar LDG, double atomics.
// ---------------------------------------------------------------------------
__global__ void __launch_bounds__(256) k_fused(const float* __restrict__ emb,
                                               const float* __restrict__ v) {
    __shared__ float sv[Ff];
    __shared__ float spart[256];
    __shared__ float red_sum[8];
    __shared__ float red_sq[8];

    int tid = threadIdx.x;
    if (tid < Ff) sv[tid] = v[tid];
    __syncthreads();

    int b  = blockIdx.x >> 5;          // 0..15
    int ng = blockIdx.x & 31;          // 0..31 (group of 64 n)
    int nl = tid & 63;                 // 0..63
    int fc = tid >> 6;                 // 0..3  (f-chunk of 32)
    int n  = ng * 64 + nl;

    const float* p  = emb + ((size_t)(b * Ff + fc * 32)) * Nn + n;
    const float* pv = sv + fc * 32;

    float s = 0.f, sum = 0.f, sq = 0.f;
#pragma unroll
    for (int f = 0; f < 32; f++) {
        float x = __ldg(p + (size_t)f * Nn);
        s   = fmaf(pv[f], x, s);
        sum += x;
        sq  = fmaf(x, x, sq);
    }
    spart[tid] = s;
    __syncthreads();
    if (tid < 64) {
        float tot = spart[tid] + spart[64 + tid] + spart[128 + tid] + spart[192 + tid];
        g_s[b * Nn + ng * 64 + tid] = tot;
    }

    // block reduce sum & sq -> double atomics
    int lane = tid & 31;
    int wid  = tid >> 5;
#pragma unroll
    for (int o = 16; o > 0; o >>= 1) {
        sum += __shfl_xor_sync(0xffffffffu, sum, o);
        sq  += __shfl_xor_sync(0xffffffffu, sq, o);
    }
    if (lane == 0) { red_sum[wid] = sum; red_sq[wid] = sq; }
    __syncthreads();
    if (wid == 0) {
        float rs = (lane < 8) ? red_sum[lane] : 0.f;
        float rq = (lane < 8) ? red_sq[lane]  : 0.f;
#pragma unroll
        for (int o = 4; o > 0; o >>= 1) {
            rs += __shfl_xor_sync(0xffffffffu, rs, o);
            rq += __shfl_xor_sync(0xffffffffu, rq, o);
        }
        if (lane == 0) {
            atomicAdd(&g_sum, (double)rs);
            atomicAdd(&g_sumsq, (double)rq);
        }
    }
}

// ---------------------------------------------------------------------------
// Pass 2: E[n] = exp(-(s[n]*scale + bias/2)). 128 blocks x 256 thr; scale
// computed per-block from the global accumulators (tid 0 -> smem broadcast).
// ---------------------------------------------------------------------------
__global__ void __launch_bounds__(256) k_exp(const float* __restrict__ bias) {
    __shared__ float sh_scale, sh_hb;
    if (threadIdx.x == 0) {
        double m   = (double)TOT;
        double var = (g_sumsq - g_sum * g_sum / m) / (m - 1.0);
        sh_scale = (float)(1.0 / sqrt(var));
        sh_hb    = 0.5f * bias[0];
    }
    __syncthreads();
    int idx = blockIdx.x * 256 + threadIdx.x;
    float t = fmaf(g_s[idx], sh_scale, sh_hb);
    g_E[idx] = __expf(-t);
}

// ---------------------------------------------------------------------------
// Pass 3: out[b,i,j] = 1 / (1 + E_i * E_j). 4 rows per block; each thread
// owns one float4 of j and writes it for all 4 rows. E_i via one aligned
// float4 load. Re-zeroes the accumulators for the next graph replay
// (invariant: zero at every kernel_launch entry; static init covers call 1).
// ---------------------------------------------------------------------------
__device__ __forceinline__ float frcp(float x) {
    float r;
    asm("rcp.approx.f32 %0, %1;" : "=f"(r) : "f"(x));
    return r;
}

__global__ void __launch_bounds__(512) k_main(float* __restrict__ out) {
    int r0 = blockIdx.x << 2;          // first of 4 rows, multiple of 4
    int b  = r0 >> 11;

    const float4* Erow = (const float4*)(g_E + (size_t)b * Nn);
    float4 ej = __ldg(Erow + threadIdx.x);

    float4 pi = __ldg((const float4*)(g_E + r0));   // E_i for the 4 rows
    float p0 = pi.x, p1 = pi.y, p2 = pi.z, p3 = pi.w;

    float4 o0, o1, o2, o3;
    o0.x = frcp(fmaf(p0, ej.x, 1.f)); o0.y = frcp(fmaf(p0, ej.y, 1.f));
    o0.z = frcp(fmaf(p0, ej.z, 1.f)); o0.w = frcp(fmaf(p0, ej.w, 1.f));
    o1.x = frcp(fmaf(p1, ej.x, 1.f)); o1.y = frcp(fmaf(p1, ej.y, 1.f));
    o1.z = frcp(fmaf(p1, ej.z, 1.f)); o1.w = frcp(fmaf(p1, ej.w, 1.f));
    o2.x = frcp(fmaf(p2, ej.x, 1.f)); o2.y = frcp(fmaf(p2, ej.y, 1.f));
    o2.z = frcp(fmaf(p2, ej.z, 1.f)); o2.w = frcp(fmaf(p2, ej.w, 1.f));
    o3.x = frcp(fmaf(p3, ej.x, 1.f)); o3.y = frcp(fmaf(p3, ej.y, 1.f));
    o3.z = frcp(fmaf(p3, ej.z, 1.f)); o3.w = frcp(fmaf(p3, ej.w, 1.f));

    float4* orow = (float4*)(out + (size_t)r0 * Nn) + threadIdx.x;
    orow[0]          = o0;
    orow[Nn / 4]     = o1;
    orow[Nn / 2]     = o2;
    orow[3 * Nn / 4] = o3;

    if (blockIdx.x == 0 && threadIdx.x == 0) {
        g_sum = 0.0;
        g_sumsq = 0.0;
    }
}

extern "C" void kernel_launch(void* const* d_in, const int* in_sizes, int n_in,
                              void* d_out, int out_size) {
    // inputs: adj_in [B,N,N] (unused), emb_in [B,F,N], v [F], b [1]
    const float* emb  = (const float*)d_in[1];
    const float* v    = (const float*)d_in[2];
    const float* bias = (const float*)d_in[3];
    float* out = (float*)d_out;

    k_fused<<<512, 256>>>(emb, v);
    k_exp<<<BN / 256, 256>>>(bias);
    k_main<<<BN / 4, 512>>>(out);
}